// round 7
// baseline (speedup 1.0000x reference)
#include <cuda_runtime.h>
#include <cstdint>

#define BATCH 8
#define DIM 32
#define NPTS 131072
#define KINST 64
#define IGNORE_IDX (-100)
#define W1 8          // warps per block in pass1
#define ROWS 65       // KINST + 1 trash row for invalid points
#define TPAD 33       // tile stride: 32 + 1 (conflict-free transpose)
#define APAD 32       // accumulator stride: row uniform across lanes -> 32 is conflict-free

// ---------------- global scratch (no allocation allowed) ----------------
__device__ float g_sums[BATCH][KINST][DIM];
__device__ float g_cnt[BATCH][KINST];
__device__ float g_lvar[BATCH];

// ---------------- kernel 0: zero scratch + output ----------------
__global__ void zero_kernel(float* out) {
    int i = blockIdx.x * blockDim.x + threadIdx.x;
    if (i < BATCH * KINST * DIM) ((float*)g_sums)[i] = 0.f;
    if (i < BATCH * KINST)       ((float*)g_cnt)[i]  = 0.f;
    if (i < BATCH)               g_lvar[i] = 0.f;
    if (i < 4)                   out[i] = 0.f;
}

// ---------------- pass 1: per-cluster counts + sums (one batch) ----------------
// Warp-private smem accumulators; transpose 32x32 point-tile through padded smem
// so lane l exclusively owns dim column l -> conflict-free, atomic-free scatter.
__global__ void pass1_kernel(const float* __restrict__ emb,
                             const int*   __restrict__ sem,
                             const int*   __restrict__ ins,
                             int b) {
    extern __shared__ float sh[];
    const int w = threadIdx.x >> 5;
    const int l = threadIdx.x & 31;

    float* wsum = sh + (size_t)w * (ROWS * APAD);                       // [65][32]
    float* tile = sh + W1 * ROWS * APAD + (size_t)w * (32 * TPAD);      // [32][33]
    float* wcnt = sh + W1 * ROWS * APAD + W1 * 32 * TPAD + (size_t)w * ROWS;

    for (int i = l; i < ROWS * APAD; i += 32) wsum[i] = 0.f;
    for (int i = l; i < ROWS;        i += 32) wcnt[i] = 0.f;

    const float* E = emb + (size_t)b * DIM * NPTS;
    const int*   S = sem + (size_t)b * NPTS;
    const int*   I = ins + (size_t)b * NPTS;

    const int NT = NPTS / 32;
    const int wg = blockIdx.x * W1 + w;
    const int nw = gridDim.x * W1;

    for (int t = wg; t < NT; t += nw) {
        const int n0 = t * 32;
        int cls = S[n0 + l];
        int id  = I[n0 + l];
        if (cls == 1)          id = 0;      // class 1 merged into instance 0
        if (cls == IGNORE_IDX) id = KINST;  // invalid -> trash row

        // per-point count, combined across equal ids within the warp
        unsigned m = __match_any_sync(0xffffffffu, id);
        if ((m & ((1u << l) - 1u)) == 0u) wcnt[id] += (float)__popc(m);

        // load 32x32 tile: step s reads dim s of 32 consecutive points (coalesced)
        // store transposed: tile[point l][dim s]; store banks (l*33+s)%32 distinct
        #pragma unroll
        for (int s = 0; s < 32; s++)
            tile[l * TPAD + s] = E[(size_t)s * NPTS + n0 + l];
        __syncwarp();

        // accumulate: serialize over points, lane l owns dim l (no atomics).
        // Row ip is uniform across lanes -> stride-32 accumulator is conflict-free.
        #pragma unroll
        for (int p = 0; p < 32; p++) {
            int ip = __shfl_sync(0xffffffffu, id, p);
            wsum[ip * APAD + l] += tile[p * TPAD + l];
        }
        __syncwarp();
    }

    // flush warp-private accumulators to global (coalesced float RED)
    for (int k = 0; k < KINST; k++)
        atomicAdd(&g_sums[b][k][l], wsum[k * APAD + l]);
    for (int k = l; k < KINST; k += 32)
        atomicAdd(&g_cnt[b][k], wcnt[k]);
}

// ---------------- pass 2: hinged intra-cluster variance (one batch) ----------------
// invc folded per-point -> single scalar reduction, no per-cluster scatter.
__global__ void pass2_kernel(const float* __restrict__ emb,
                             const int*   __restrict__ sem,
                             const int*   __restrict__ ins,
                             int b) {
    __shared__ float mu[KINST * TPAD];
    __shared__ float invc[KINST];
    __shared__ float red[8];
    const int tid = threadIdx.x;

    for (int i = tid; i < KINST; i += blockDim.x)
        invc[i] = 1.f / (g_cnt[b][i] + 1e-8f);
    __syncthreads();
    for (int i = tid; i < KINST * DIM; i += blockDim.x) {
        int k = i >> 5, d = i & 31;
        mu[k * TPAD + d] = g_sums[b][k][d] * invc[k];
    }
    __syncthreads();

    const float* E = emb + (size_t)b * DIM * NPTS;
    const int*   S = sem + (size_t)b * NPTS;
    const int*   I = ins + (size_t)b * NPTS;

    float acc = 0.f;
    const int stride = gridDim.x * blockDim.x;
    for (int n = blockIdx.x * blockDim.x + tid; n < NPTS; n += stride) {
        int cls = S[n];
        int id  = I[n];
        if (cls == 1) id = 0;
        if (cls != IGNORE_IDX) {
            const float* mrow = &mu[id * TPAD];
            float d0 = 0.f, d1 = 0.f, d2 = 0.f, d3 = 0.f;
            #pragma unroll
            for (int d = 0; d < 32; d += 4) {
                d0 += fabsf(E[(size_t)(d + 0) * NPTS + n] - mrow[d + 0]);
                d1 += fabsf(E[(size_t)(d + 1) * NPTS + n] - mrow[d + 1]);
                d2 += fabsf(E[(size_t)(d + 2) * NPTS + n] - mrow[d + 2]);
                d3 += fabsf(E[(size_t)(d + 3) * NPTS + n] - mrow[d + 3]);
            }
            float dist = (d0 + d1) + (d2 + d3);
            float h = fmaxf(dist - 0.5f, 0.f);
            acc += h * h * invc[id];
        }
    }

    // block reduce -> one global atomic per block
    #pragma unroll
    for (int o = 16; o > 0; o >>= 1) acc += __shfl_down_sync(0xffffffffu, acc, o);
    if ((tid & 31) == 0) red[tid >> 5] = acc;
    __syncthreads();
    if (tid < 8) {
        float r = red[tid];
        #pragma unroll
        for (int o = 4; o > 0; o >>= 1) r += __shfl_down_sync(0xffu, r, o);
        if (tid == 0) atomicAdd(&g_lvar[b], r);
    }
}

// ---------------- finalize: l_dist, l_reg, combine, mean over batches ----------------
__device__ __forceinline__ float block_reduce_256(float v, float* red8, float* bc) {
    const int tid = threadIdx.x;
    #pragma unroll
    for (int o = 16; o > 0; o >>= 1) v += __shfl_down_sync(0xffffffffu, v, o);
    if ((tid & 31) == 0) red8[tid >> 5] = v;
    __syncthreads();
    if (tid < 8) {
        float r = red8[tid];
        #pragma unroll
        for (int o = 4; o > 0; o >>= 1) r += __shfl_down_sync(0xffu, r, o);
        if (tid == 0) *bc = r;
    }
    __syncthreads();
    float res = *bc;
    __syncthreads();
    return res;
}

__global__ void finalize_kernel(float* out) {
    const int b   = blockIdx.x;
    const int tid = threadIdx.x;
    __shared__ float mu[KINST * TPAD];
    __shared__ float cnts[KINST];
    __shared__ float red8[8];
    __shared__ float bc;

    for (int i = tid; i < KINST; i += blockDim.x) cnts[i] = g_cnt[b][i];
    __syncthreads();
    for (int i = tid; i < KINST * DIM; i += blockDim.x) {
        int k = i >> 5, d = i & 31;
        mu[k * TPAD + d] = g_sums[b][k][d] / (cnts[k] + 1e-8f);
    }
    __syncthreads();

    // present count + l_reg partials
    float pr = 0.f, lreg = 0.f;
    for (int k = tid; k < KINST; k += blockDim.x) {
        if (cnts[k] > 0.f) {
            pr += 1.f;
            float s = 0.f;
            #pragma unroll
            for (int d = 0; d < DIM; d++) s += fabsf(mu[k * TPAD + d]);
            lreg += s;
        }
    }

    // pairwise hinge over present cluster pairs (i != j)
    float hs = 0.f, np = 0.f;
    for (int pidx = tid; pidx < KINST * KINST; pidx += blockDim.x) {
        int i = pidx >> 6, j = pidx & 63;
        if (i != j && cnts[i] > 0.f && cnts[j] > 0.f) {
            float pd = 0.f;
            #pragma unroll
            for (int d = 0; d < DIM; d++)
                pd += fabsf(mu[i * TPAD + d] - mu[j * TPAD + d]);
            float h = fmaxf(3.0f - pd, 0.f);  // 2 * DELTA_D - pdist
            hs += h * h;
            np += 1.f;
        }
    }

    float pr_t   = block_reduce_256(pr,   red8, &bc);
    float lreg_t = block_reduce_256(lreg, red8, &bc);
    float hs_t   = block_reduce_256(hs,   red8, &bc);
    float np_t   = block_reduce_256(np,   red8, &bc);

    if (tid == 0) {
        float n_inst = fmaxf(pr_t, 1.f);
        float l_var  = g_lvar[b] / n_inst;                            // PARAM_VAR = 1
        float l_dist = (np_t > 0.f) ? hs_t / fmaxf(np_t, 1.f) : 0.f;  // PARAM_DIST = 1
        float l_reg  = 0.001f * (lreg_t / n_inst);                    // PARAM_REG
        float loss   = l_var + l_dist + l_reg;                        // LOSS_WEIGHT = 1
        const float inv_b = 1.f / (float)BATCH;
        atomicAdd(&out[0], loss   * inv_b);
        atomicAdd(&out[1], l_var  * inv_b);
        atomicAdd(&out[2], l_dist * inv_b);
        atomicAdd(&out[3], l_reg  * inv_b);
    }
}

// ---------------- launch ----------------
extern "C" void kernel_launch(void* const* d_in, const int* in_sizes, int n_in,
                              void* d_out, int out_size) {
    const float* emb = (const float*)d_in[0];
    const int*   sem = (const int*)d_in[1];
    const int*   ins = (const int*)d_in[2];
    float*       out = (float*)d_out;

    const int SMEM1 = (W1 * ROWS * APAD + W1 * 32 * TPAD + W1 * ROWS) * 4;
    cudaFuncSetAttribute(pass1_kernel,
                         cudaFuncAttributeMaxDynamicSharedMemorySize, SMEM1);

    zero_kernel<<<64, 256>>>(out);
    // per-batch interleave: pass2(b) re-reads the 16 MB slice pass1(b) just
    // pulled -> mostly L2 hits instead of a second full HBM pass
    for (int b = 0; b < BATCH; b++) {
        pass1_kernel<<<304, 256, SMEM1>>>(emb, sem, ins, b);
        pass2_kernel<<<304, 256>>>(emb, sem, ins, b);
    }
    finalize_kernel<<<BATCH, 256>>>(out);
}

// round 9
// speedup vs baseline: 2.2277x; 2.2277x over previous
#include <cuda_runtime.h>
#include <cstdint>

#define BATCH 8
#define DIM 32
#define NPTS 131072
#define KINST 64
#define IGNORE_IDX (-100)
#define W1 8          // warps per block in pass1
#define ROWS 65       // KINST + 1 trash row for invalid points
#define TPAD 33       // tile stride: 32 + 1 (conflict-free transpose)
#define APAD 32       // accumulator stride: row uniform across lanes -> conflict-free
#define NT_B (NPTS / 32)     // 4096 tiles per batch
#define GRID1 304            // 8 batches * 38 blocks = 2 CTAs x 152 SMs
#define BPB (GRID1 / BATCH)  // 38 blocks per batch

// ---------------- global scratch (no allocation allowed) ----------------
__device__ float g_sums[BATCH][KINST][DIM];
__device__ float g_cnt[BATCH][KINST];
__device__ float g_lvar[BATCH];

// ---------------- kernel 0: zero scratch + output ----------------
__global__ void zero_kernel(float* out) {
    int i = blockIdx.x * blockDim.x + threadIdx.x;
    if (i < BATCH * KINST * DIM) ((float*)g_sums)[i] = 0.f;
    if (i < BATCH * KINST)       ((float*)g_cnt)[i]  = 0.f;
    if (i < BATCH)               g_lvar[i] = 0.f;
    if (i < 4)                   out[i] = 0.f;
}

// ---------------- pass 1: per-cluster counts + sums, ALL batches ----------------
// Warp-private smem accumulators (atomic-free scatter via 32x32 transpose),
// then a block-level smem reduction so only ONE atomicAdd set per block hits L2.
__global__ void pass1_kernel(const float* __restrict__ emb,
                             const int*   __restrict__ sem,
                             const int*   __restrict__ ins) {
    extern __shared__ float sh[];
    const int w = threadIdx.x >> 5;
    const int l = threadIdx.x & 31;
    const int b   = blockIdx.x & (BATCH - 1);   // batch of this block
    const int blk = blockIdx.x >> 3;            // 0..BPB-1 within batch

    float* wsum = sh + (size_t)w * (ROWS * APAD);                       // [65][32] per warp
    float* tile = sh + W1 * ROWS * APAD + (size_t)w * (32 * TPAD);      // [32][33] per warp
    float* cnts = sh + W1 * ROWS * APAD + W1 * 32 * TPAD;               // [W1][65]
    float* wcnt = cnts + (size_t)w * ROWS;

    for (int i = l; i < ROWS * APAD; i += 32) wsum[i] = 0.f;
    for (int i = l; i < ROWS;        i += 32) wcnt[i] = 0.f;

    const float* E = emb + (size_t)b * DIM * NPTS;
    const int*   S = sem + (size_t)b * NPTS;
    const int*   I = ins + (size_t)b * NPTS;

    for (int t = blk * W1 + w; t < NT_B; t += BPB * W1) {
        const int n0 = t * 32;
        int cls = S[n0 + l];
        int id  = I[n0 + l];
        if (cls == 1)          id = 0;      // class 1 merged into instance 0
        if (cls == IGNORE_IDX) id = KINST;  // invalid -> trash row

        // per-point count, combined across equal ids within the warp
        unsigned m = __match_any_sync(0xffffffffu, id);
        if ((m & ((1u << l) - 1u)) == 0u) wcnt[id] += (float)__popc(m);

        // load 32x32 tile: step s reads dim s of 32 consecutive points (coalesced)
        // store transposed: tile[point l][dim s] (stride 33 -> conflict-free)
        #pragma unroll
        for (int s = 0; s < 32; s++)
            tile[l * TPAD + s] = E[(size_t)s * NPTS + n0 + l];
        __syncwarp();

        // accumulate: serialize over points, lane l owns dim l (no atomics).
        // Row ip is uniform across lanes -> stride-32 accumulator conflict-free.
        #pragma unroll
        for (int p = 0; p < 32; p++) {
            int ip = __shfl_sync(0xffffffffu, id, p);
            wsum[ip * APAD + l] += tile[p * TPAD + l];
        }
        __syncwarp();
    }
    __syncthreads();

    // block-level reduction of the 8 warp accumulators -> ONE atomic set/block
    if (threadIdx.x < KINST) {
        float c = 0.f;
        #pragma unroll
        for (int ww = 0; ww < W1; ww++)
            c += cnts[(size_t)ww * ROWS + threadIdx.x];
        atomicAdd(&g_cnt[b][threadIdx.x], c);
    }
    for (int r = w; r < KINST; r += W1) {
        float s = 0.f;
        #pragma unroll
        for (int ww = 0; ww < W1; ww++)
            s += sh[(size_t)ww * (ROWS * APAD) + r * APAD + l];
        atomicAdd(&g_sums[b][r][l], s);
    }
}

// ---------------- pass 2: hinged intra-cluster variance, ALL batches ----------------
// invc folded per-point -> single scalar reduction, no per-cluster scatter.
__global__ void pass2_kernel(const float* __restrict__ emb,
                             const int*   __restrict__ sem,
                             const int*   __restrict__ ins) {
    __shared__ float mu[KINST * TPAD];
    __shared__ float invc[KINST];
    __shared__ float red[8];
    const int tid = threadIdx.x;
    const int b   = blockIdx.x & (BATCH - 1);
    const int blk = blockIdx.x >> 3;            // 0..BPB-1 within batch

    for (int i = tid; i < KINST; i += blockDim.x)
        invc[i] = 1.f / (g_cnt[b][i] + 1e-8f);
    __syncthreads();
    for (int i = tid; i < KINST * DIM; i += blockDim.x) {
        int k = i >> 5, d = i & 31;
        mu[k * TPAD + d] = g_sums[b][k][d] * invc[k];
    }
    __syncthreads();

    const float* E = emb + (size_t)b * DIM * NPTS;
    const int*   S = sem + (size_t)b * NPTS;
    const int*   I = ins + (size_t)b * NPTS;

    float acc = 0.f;
    const int stride = BPB * blockDim.x;
    for (int n = blk * blockDim.x + tid; n < NPTS; n += stride) {
        int cls = S[n];
        int id  = I[n];
        if (cls == 1) id = 0;
        if (cls != IGNORE_IDX) {
            const float* mrow = &mu[id * TPAD];
            float d0 = 0.f, d1 = 0.f, d2 = 0.f, d3 = 0.f;
            #pragma unroll
            for (int d = 0; d < 32; d += 4) {
                d0 += fabsf(E[(size_t)(d + 0) * NPTS + n] - mrow[d + 0]);
                d1 += fabsf(E[(size_t)(d + 1) * NPTS + n] - mrow[d + 1]);
                d2 += fabsf(E[(size_t)(d + 2) * NPTS + n] - mrow[d + 2]);
                d3 += fabsf(E[(size_t)(d + 3) * NPTS + n] - mrow[d + 3]);
            }
            float dist = (d0 + d1) + (d2 + d3);
            float h = fmaxf(dist - 0.5f, 0.f);
            acc += h * h * invc[id];
        }
    }

    // block reduce -> one global atomic per block
    #pragma unroll
    for (int o = 16; o > 0; o >>= 1) acc += __shfl_down_sync(0xffffffffu, acc, o);
    if ((tid & 31) == 0) red[tid >> 5] = acc;
    __syncthreads();
    if (tid < 8) {
        float r = red[tid];
        #pragma unroll
        for (int o = 4; o > 0; o >>= 1) r += __shfl_down_sync(0xffu, r, o);
        if (tid == 0) atomicAdd(&g_lvar[b], r);
    }
}

// ---------------- finalize: l_dist, l_reg, combine, mean over batches ----------------
__device__ __forceinline__ float block_reduce_256(float v, float* red8, float* bc) {
    const int tid = threadIdx.x;
    #pragma unroll
    for (int o = 16; o > 0; o >>= 1) v += __shfl_down_sync(0xffffffffu, v, o);
    if ((tid & 31) == 0) red8[tid >> 5] = v;
    __syncthreads();
    if (tid < 8) {
        float r = red8[tid];
        #pragma unroll
        for (int o = 4; o > 0; o >>= 1) r += __shfl_down_sync(0xffu, r, o);
        if (tid == 0) *bc = r;
    }
    __syncthreads();
    float res = *bc;
    __syncthreads();
    return res;
}

__global__ void finalize_kernel(float* out) {
    const int b   = blockIdx.x;
    const int tid = threadIdx.x;
    __shared__ float mu[KINST * TPAD];
    __shared__ float cnts[KINST];
    __shared__ float red8[8];
    __shared__ float bc;

    for (int i = tid; i < KINST; i += blockDim.x) cnts[i] = g_cnt[b][i];
    __syncthreads();
    for (int i = tid; i < KINST * DIM; i += blockDim.x) {
        int k = i >> 5, d = i & 31;
        mu[k * TPAD + d] = g_sums[b][k][d] / (cnts[k] + 1e-8f);
    }
    __syncthreads();

    // present count + l_reg partials
    float pr = 0.f, lreg = 0.f;
    for (int k = tid; k < KINST; k += blockDim.x) {
        if (cnts[k] > 0.f) {
            pr += 1.f;
            float s = 0.f;
            #pragma unroll
            for (int d = 0; d < DIM; d++) s += fabsf(mu[k * TPAD + d]);
            lreg += s;
        }
    }

    // pairwise hinge over present cluster pairs (i != j)
    float hs = 0.f, np = 0.f;
    for (int pidx = tid; pidx < KINST * KINST; pidx += blockDim.x) {
        int i = pidx >> 6, j = pidx & 63;
        if (i != j && cnts[i] > 0.f && cnts[j] > 0.f) {
            float pd = 0.f;
            #pragma unroll
            for (int d = 0; d < DIM; d++)
                pd += fabsf(mu[i * TPAD + d] - mu[j * TPAD + d]);
            float h = fmaxf(3.0f - pd, 0.f);  // 2 * DELTA_D - pdist
            hs += h * h;
            np += 1.f;
        }
    }

    float pr_t   = block_reduce_256(pr,   red8, &bc);
    float lreg_t = block_reduce_256(lreg, red8, &bc);
    float hs_t   = block_reduce_256(hs,   red8, &bc);
    float np_t   = block_reduce_256(np,   red8, &bc);

    if (tid == 0) {
        float n_inst = fmaxf(pr_t, 1.f);
        float l_var  = g_lvar[b] / n_inst;                            // PARAM_VAR = 1
        float l_dist = (np_t > 0.f) ? hs_t / fmaxf(np_t, 1.f) : 0.f;  // PARAM_DIST = 1
        float l_reg  = 0.001f * (lreg_t / n_inst);                    // PARAM_REG
        float loss   = l_var + l_dist + l_reg;                        // LOSS_WEIGHT = 1
        const float inv_b = 1.f / (float)BATCH;
        atomicAdd(&out[0], loss   * inv_b);
        atomicAdd(&out[1], l_var  * inv_b);
        atomicAdd(&out[2], l_dist * inv_b);
        atomicAdd(&out[3], l_reg  * inv_b);
    }
}

// ---------------- launch ----------------
extern "C" void kernel_launch(void* const* d_in, const int* in_sizes, int n_in,
                              void* d_out, int out_size) {
    const float* emb = (const float*)d_in[0];
    const int*   sem = (const int*)d_in[1];
    const int*   ins = (const int*)d_in[2];
    float*       out = (float*)d_out;

    const int SMEM1 = (W1 * ROWS * APAD + W1 * 32 * TPAD + W1 * ROWS) * 4;
    cudaFuncSetAttribute(pass1_kernel,
                         cudaFuncAttributeMaxDynamicSharedMemorySize, SMEM1);

    zero_kernel<<<64, 256>>>(out);
    pass1_kernel<<<GRID1, 256, SMEM1>>>(emb, sem, ins);   // all batches, one wave
    pass2_kernel<<<GRID1, 256>>>(emb, sem, ins);          // all batches
    finalize_kernel<<<BATCH, 256>>>(out);
}

// round 11
// speedup vs baseline: 2.5957x; 1.1652x over previous
#include <cuda_runtime.h>
#include <cstdint>

#define BATCH 8
#define DIM 32
#define NPTS 131072
#define KINST 64
#define IGNORE_IDX (-100)
#define W1 8          // warps per block in pass1
#define ROWS 65       // KINST + 1 trash row for invalid points
#define TPAD 33       // stride 32 + 1 (conflict-free for varying-row access)
#define APAD 32       // accumulator stride: row uniform across lanes -> conflict-free
#define NT_B (NPTS / 32)     // 4096 tiles per batch
#define GRID1 304            // 8 batches * 38 blocks = 2 CTAs x 152 SMs
#define BPB (GRID1 / BATCH)  // 38 blocks per batch

// ---------------- global scratch (no allocation allowed) ----------------
__device__ float        g_sums[BATCH][KINST][DIM];
__device__ float        g_cnt[BATCH][KINST];
__device__ float        g_lvar[BATCH];
__device__ unsigned int g_ticket[BATCH];

// ---------------- kernel 0: zero scratch + output ----------------
__global__ void zero_kernel(float* out) {
    int i = blockIdx.x * blockDim.x + threadIdx.x;
    if (i < BATCH * KINST * DIM) ((float*)g_sums)[i] = 0.f;
    if (i < BATCH * KINST)       ((float*)g_cnt)[i]  = 0.f;
    if (i < BATCH)             { g_lvar[i] = 0.f; g_ticket[i] = 0u; }
    if (i < 4)                   out[i] = 0.f;
}

// ---------------- pass 1: per-cluster counts + sums, ALL batches ----------------
// Warp-private smem accumulators (atomic-free scatter via 32x32 transpose),
// then a block-level smem reduction so only ONE atomicAdd set per block hits L2.
__global__ __launch_bounds__(256) void pass1_kernel(const float* __restrict__ emb,
                                                    const int*   __restrict__ sem,
                                                    const int*   __restrict__ ins) {
    extern __shared__ float sh[];
    const int w = threadIdx.x >> 5;
    const int l = threadIdx.x & 31;
    const int b   = blockIdx.x & (BATCH - 1);   // batch of this block
    const int blk = blockIdx.x >> 3;            // 0..BPB-1 within batch

    float* wsum = sh + (size_t)w * (ROWS * APAD);                       // [65][32] per warp
    float* tile = sh + W1 * ROWS * APAD + (size_t)w * (32 * TPAD);      // [32][33] per warp
    float* cnts = sh + W1 * ROWS * APAD + W1 * 32 * TPAD;               // [W1][65]
    float* wcnt = cnts + (size_t)w * ROWS;

    for (int i = l; i < ROWS * APAD; i += 32) wsum[i] = 0.f;
    for (int i = l; i < ROWS;        i += 32) wcnt[i] = 0.f;

    const float* E = emb + (size_t)b * DIM * NPTS;
    const int*   S = sem + (size_t)b * NPTS;
    const int*   I = ins + (size_t)b * NPTS;

    for (int t = blk * W1 + w; t < NT_B; t += BPB * W1) {
        const int n0 = t * 32;
        int cls = S[n0 + l];
        int id  = I[n0 + l];
        if (cls == 1)          id = 0;      // class 1 merged into instance 0
        if (cls == IGNORE_IDX) id = KINST;  // invalid -> trash row

        // per-point count, combined across equal ids within the warp
        unsigned m = __match_any_sync(0xffffffffu, id);
        if ((m & ((1u << l) - 1u)) == 0u) wcnt[id] += (float)__popc(m);

        // load 32x32 tile: step s reads dim s of 32 consecutive points (coalesced)
        // store transposed: tile[point l][dim s] (stride 33 -> conflict-free)
        #pragma unroll
        for (int s = 0; s < 32; s++)
            tile[l * TPAD + s] = E[(size_t)s * NPTS + n0 + l];
        __syncwarp();

        // accumulate: serialize over points, lane l owns dim l (no atomics).
        // Row ip is uniform across lanes -> stride-32 accumulator conflict-free.
        #pragma unroll
        for (int p = 0; p < 32; p++) {
            int ip = __shfl_sync(0xffffffffu, id, p);
            wsum[ip * APAD + l] += tile[p * TPAD + l];
        }
        __syncwarp();
    }
    __syncthreads();

    // block-level reduction of the 8 warp accumulators -> ONE atomic set/block
    if (threadIdx.x < KINST) {
        float c = 0.f;
        #pragma unroll
        for (int ww = 0; ww < W1; ww++)
            c += cnts[(size_t)ww * ROWS + threadIdx.x];
        atomicAdd(&g_cnt[b][threadIdx.x], c);
    }
    for (int r = w; r < KINST; r += W1) {
        float s = 0.f;
        #pragma unroll
        for (int ww = 0; ww < W1; ww++)
            s += sh[(size_t)ww * (ROWS * APAD) + r * APAD + l];
        atomicAdd(&g_sums[b][r][l], s);
    }
}

// ---------------- block reduce helper ----------------
__device__ __forceinline__ float block_reduce_256(float v, float* red8, float* bc) {
    const int tid = threadIdx.x;
    #pragma unroll
    for (int o = 16; o > 0; o >>= 1) v += __shfl_down_sync(0xffffffffu, v, o);
    if ((tid & 31) == 0) red8[tid >> 5] = v;
    __syncthreads();
    if (tid < 8) {
        float r = red8[tid];
        #pragma unroll
        for (int o = 4; o > 0; o >>= 1) r += __shfl_down_sync(0xffu, r, o);
        if (tid == 0) *bc = r;
    }
    __syncthreads();
    float res = *bc;
    __syncthreads();
    return res;
}

// ---------------- pass 2: hinged variance (float4) + FUSED finalize ----------------
__global__ __launch_bounds__(256) void pass2_kernel(const float* __restrict__ emb,
                                                    const int*   __restrict__ sem,
                                                    const int*   __restrict__ ins,
                                                    float* __restrict__ out) {
    __shared__ float mu[KINST * TPAD];
    __shared__ float invc[KINST];
    __shared__ float cs[KINST];
    __shared__ float red8[8];
    __shared__ float bc;
    __shared__ int   last_flag;
    const int tid = threadIdx.x;
    const int b   = blockIdx.x & (BATCH - 1);
    const int blk = blockIdx.x >> 3;            // 0..BPB-1 within batch

    for (int i = tid; i < KINST; i += blockDim.x) {
        float c = g_cnt[b][i];
        cs[i]   = c;
        invc[i] = 1.f / (c + 1e-8f);
    }
    __syncthreads();
    for (int i = tid; i < KINST * DIM; i += blockDim.x) {
        int k = i >> 5, d = i & 31;
        mu[k * TPAD + d] = g_sums[b][k][d] * invc[k];
    }
    __syncthreads();

    const float* E = emb + (size_t)b * DIM * NPTS;
    const int*   S = sem + (size_t)b * NPTS;
    const int*   I = ins + (size_t)b * NPTS;

    float acc = 0.f;
    const int NQ = NPTS / 4;
    for (int q = blk * blockDim.x + tid; q < NQ; q += BPB * blockDim.x) {
        int4 c4 = ((const int4*)S)[q];
        int4 i4 = ((const int4*)I)[q];
        bool v0 = (c4.x != IGNORE_IDX), v1 = (c4.y != IGNORE_IDX);
        bool v2 = (c4.z != IGNORE_IDX), v3 = (c4.w != IGNORE_IDX);
        int id0 = (c4.x == 1) ? 0 : i4.x; if (!v0) id0 = 0;
        int id1 = (c4.y == 1) ? 0 : i4.y; if (!v1) id1 = 0;
        int id2 = (c4.z == 1) ? 0 : i4.z; if (!v2) id2 = 0;
        int id3 = (c4.w == 1) ? 0 : i4.w; if (!v3) id3 = 0;
        const float* m0 = &mu[id0 * TPAD];
        const float* m1 = &mu[id1 * TPAD];
        const float* m2 = &mu[id2 * TPAD];
        const float* m3 = &mu[id3 * TPAD];

        float s0 = 0.f, s1 = 0.f, s2 = 0.f, s3 = 0.f;
        #pragma unroll
        for (int d = 0; d < 32; d++) {
            float4 v = ((const float4*)(E + (size_t)d * NPTS))[q];
            s0 += fabsf(v.x - m0[d]);
            s1 += fabsf(v.y - m1[d]);
            s2 += fabsf(v.z - m2[d]);
            s3 += fabsf(v.w - m3[d]);
        }
        float h0 = fmaxf(s0 - 0.5f, 0.f);
        float h1 = fmaxf(s1 - 0.5f, 0.f);
        float h2 = fmaxf(s2 - 0.5f, 0.f);
        float h3 = fmaxf(s3 - 0.5f, 0.f);
        if (v0) acc += h0 * h0 * invc[id0];
        if (v1) acc += h1 * h1 * invc[id1];
        if (v2) acc += h2 * h2 * invc[id2];
        if (v3) acc += h3 * h3 * invc[id3];
    }

    // block reduce lvar -> one atomic per block, then completion ticket
    float tot = block_reduce_256(acc, red8, &bc);
    if (tid == 0) {
        atomicAdd(&g_lvar[b], tot);
        __threadfence();
        unsigned prev = atomicAdd(&g_ticket[b], 1u);
        last_flag = (prev == (unsigned)(BPB - 1)) ? 1 : 0;
    }
    __syncthreads();
    if (!last_flag) return;

    // ---- fused finalize: only the last block of batch b runs this ----
    // mu / cs / invc are still resident in this block's smem.
    float pr = 0.f, lreg = 0.f;
    for (int k = tid; k < KINST; k += blockDim.x) {
        if (cs[k] > 0.f) {
            pr += 1.f;
            float s = 0.f;
            #pragma unroll
            for (int d = 0; d < DIM; d++) s += fabsf(mu[k * TPAD + d]);
            lreg += s;
        }
    }
    float hs = 0.f, np = 0.f;
    for (int pidx = tid; pidx < KINST * KINST; pidx += blockDim.x) {
        int i = pidx >> 6, j = pidx & 63;
        if (i != j && cs[i] > 0.f && cs[j] > 0.f) {
            float pd = 0.f;
            #pragma unroll
            for (int d = 0; d < DIM; d++)
                pd += fabsf(mu[i * TPAD + d] - mu[j * TPAD + d]);
            float h = fmaxf(3.0f - pd, 0.f);  // 2 * DELTA_D - pdist
            hs += h * h;
            np += 1.f;
        }
    }

    float pr_t   = block_reduce_256(pr,   red8, &bc);
    float lreg_t = block_reduce_256(lreg, red8, &bc);
    float hs_t   = block_reduce_256(hs,   red8, &bc);
    float np_t   = block_reduce_256(np,   red8, &bc);

    if (tid == 0) {
        float lv     = atomicAdd(&g_lvar[b], 0.f);   // fresh L2 read of full sum
        float n_inst = fmaxf(pr_t, 1.f);
        float l_var  = lv / n_inst;                                   // PARAM_VAR = 1
        float l_dist = (np_t > 0.f) ? hs_t / fmaxf(np_t, 1.f) : 0.f;  // PARAM_DIST = 1
        float l_reg  = 0.001f * (lreg_t / n_inst);                    // PARAM_REG
        float loss   = l_var + l_dist + l_reg;                        // LOSS_WEIGHT = 1
        const float inv_b = 1.f / (float)BATCH;
        atomicAdd(&out[0], loss   * inv_b);
        atomicAdd(&out[1], l_var  * inv_b);
        atomicAdd(&out[2], l_dist * inv_b);
        atomicAdd(&out[3], l_reg  * inv_b);
    }
}

// ---------------- launch ----------------
extern "C" void kernel_launch(void* const* d_in, const int* in_sizes, int n_in,
                              void* d_out, int out_size) {
    const float* emb = (const float*)d_in[0];
    const int*   sem = (const int*)d_in[1];
    const int*   ins = (const int*)d_in[2];
    float*       out = (float*)d_out;

    const int SMEM1 = (W1 * ROWS * APAD + W1 * 32 * TPAD + W1 * ROWS) * 4;
    cudaFuncSetAttribute(pass1_kernel,
                         cudaFuncAttributeMaxDynamicSharedMemorySize, SMEM1);

    zero_kernel<<<64, 256>>>(out);
    pass1_kernel<<<GRID1, 256, SMEM1>>>(emb, sem, ins);        // all batches, one wave
    pass2_kernel<<<GRID1, 256>>>(emb, sem, ins, out);          // variance + fused finalize
}